// round 2
// baseline (speedup 1.0000x reference)
#include <cuda_runtime.h>
#include <cstdint>

#define N_IMG 64
#define CIN   128
#define COUT  128
#define HH    56
#define WW    56
#define HW    (HH*WW)      /* 3136 */
#define HP    58
#define WP    58
#define PHW   (HP*WP)      /* 3364 */

// Padded packed sign bits of activation: [n][hp][wp] -> uint4 (128 channels, bit=1 means +1)
__device__ uint4 g_px[N_IMG * PHW];          // 3.44 MB
// Packed sign bits of weights: [o][tap] -> uint4
__device__ uint4 g_pw[COUT * 9];
// Per-channel factor: -2 * scale_o * bn_inv
__device__ float g_A[COUT];
// Border-type-folded bias (includes +1152*A term): [type 0..8][o]
__device__ float g_Bc[9 * COUT];

// ---------------------------------------------------------------------------
// Kernel 1: fused zero+pack over the padded array. One thread per padded cell.
// ---------------------------------------------------------------------------
__global__ void pack_x_kernel(const float* __restrict__ x) {
    int i = blockIdx.x * 256 + threadIdx.x;          // 0 .. 215295
    if (i >= N_IMG * PHW) return;
    int n  = i / PHW;
    int c  = i - n * PHW;
    int hp = c / WP, wp = c - hp * WP;
    if (hp == 0 || hp == HP - 1 || wp == 0 || wp == WP - 1) {
        g_px[i] = make_uint4(0u, 0u, 0u, 0u);
        return;
    }
    int hw = (hp - 1) * WW + (wp - 1);
    const float* xp = x + (size_t)n * CIN * HW + hw;

    uint32_t w0 = 0u, w1 = 0u, w2 = 0u, w3 = 0u;
#pragma unroll 8
    for (int cc = 0; cc < 32; cc++) {
        w0 |= ((__float_as_uint(xp[(size_t)(cc      ) * HW]) >> 31) ^ 1u) << cc;
        w1 |= ((__float_as_uint(xp[(size_t)(cc + 32 ) * HW]) >> 31) ^ 1u) << cc;
        w2 |= ((__float_as_uint(xp[(size_t)(cc + 64 ) * HW]) >> 31) ^ 1u) << cc;
        w3 |= ((__float_as_uint(xp[(size_t)(cc + 96 ) * HW]) >> 31) ^ 1u) << cc;
    }
    g_px[i] = make_uint4(w0, w1, w2, w3);
}

// ---------------------------------------------------------------------------
// Kernel 2: weight prep. One block (128 threads) per output channel.
// ---------------------------------------------------------------------------
__global__ void prep_w_kernel(const float* __restrict__ wgt,
                              const float* __restrict__ gamma,
                              const float* __restrict__ beta,
                              const float* __restrict__ bn_mean,
                              const float* __restrict__ bn_var) {
    int o   = blockIdx.x;
    int tid = threadIdx.x;                      // 128 threads
    __shared__ float s_red[128];
    __shared__ int   s_wpop[9];
    __shared__ float sA, sBb;

    const float* wo = wgt + (size_t)o * CIN * 9;

    float s = 0.f;
#pragma unroll
    for (int t = 0; t < 9; t++) s += fabsf(wo[tid * 9 + t]);
    s_red[tid] = s;
    __syncthreads();
    for (int k = 64; k > 0; k >>= 1) {
        if (tid < k) s_red[tid] += s_red[tid + k];
        __syncthreads();
    }

    if (tid < 9) {
        int t = tid;
        uint32_t wd[4] = {0u, 0u, 0u, 0u};
        for (int c = 0; c < CIN; c++) {
            uint32_t b = ((__float_as_uint(wo[(size_t)c * 9 + t]) >> 31) ^ 1u) & 1u;
            wd[c >> 5] |= b << (c & 31);
        }
        g_pw[o * 9 + t] = make_uint4(wd[0], wd[1], wd[2], wd[3]);
        s_wpop[t] = __popc(wd[0]) + __popc(wd[1]) + __popc(wd[2]) + __popc(wd[3]);
    }
    if (tid == 0) {
        float scale = s_red[0] * (1.0f / 1152.0f);
        float inv   = gamma[o] * rsqrtf(bn_var[o] + 1e-5f);
        sA  = scale * inv;
        sBb = beta[o] - bn_mean[o] * inv;
        g_A[o] = -2.0f * sA;                 // folded: r = A*(1152-2acc)+B = (-2A)*acc + (B+1152A)
    }
    __syncthreads();

    if (tid < 9) {
        int type = tid;
        int rt = type / 3, ct = type - rt * 3;
        int corr = 0;
#pragma unroll
        for (int t = 0; t < 9; t++) {
            int dh = t / 3, dw = t - dh * 3;
            bool inval = (rt == 0 && dh == 0) || (rt == 2 && dh == 2) ||
                         (ct == 0 && dw == 0) || (ct == 2 && dw == 2);
            if (inval) corr += 128 - 2 * s_wpop[t];
        }
        g_Bc[type * COUT + o] = sBb - sA * (float)corr + 1152.0f * sA;
    }
}

// ---------------------------------------------------------------------------
// Kernel 3: XNOR-popcount conv + BN + residual. One thread per PIXEL PAIR
// (h, 2w)/(h, 2w+1): shared weight loads, 2 independent accumulator chains,
// float2 residual/output, 12-cell neighborhood.
// ---------------------------------------------------------------------------
__global__ __launch_bounds__(128, 7) void conv_kernel(const float* __restrict__ x,
                                                      float* __restrict__ out) {
    __shared__ uint4 s_w[COUT * 9];      // 18 KB
    __shared__ float s_A[COUT];
    __shared__ float s_Bc[9 * COUT];     // 4.5 KB

    int tid = threadIdx.x;
    for (int i = tid; i < COUT * 9; i += 128) s_w[i] = g_pw[i];
    for (int i = tid; i < COUT;     i += 128) s_A[i] = g_A[i];
    for (int i = tid; i < 9 * COUT; i += 128) s_Bc[i] = g_Bc[i];
    __syncthreads();

    int t = blockIdx.x * 128 + tid;          // 0 .. 100351 (grid exact: 784*128)
    int n = t / (HW / 2);
    int q = t - n * (HW / 2);                // pair index within image
    int h = q / (WW / 2);
    int w0 = (q - h * (WW / 2)) * 2;         // 0,2,...,54

    // 3x4 neighborhood of packed activations (zero-padded)
    const uint4* base = g_px + n * PHW + h * WP + w0;
    uint4 nb[12];
#pragma unroll
    for (int dh = 0; dh < 3; dh++)
#pragma unroll
        for (int dw = 0; dw < 4; dw++)
            nb[dh * 4 + dw] = base[dh * WP + dw];

    int rt  = (h == 0) ? 0 : ((h == HH - 1) ? 2 : 1);
    int ct0 = (w0 == 0) ? 0 : 1;                 // w0 even, never right edge
    int ct1 = (w0 + 1 == WW - 1) ? 2 : 1;        // w0+1 odd, never left edge
    const float* bc0 = s_Bc + (rt * 3 + ct0) * COUT;
    const float* bc1 = s_Bc + (rt * 3 + ct1) * COUT;

    int hw = h * WW + w0;
    const float2* xr   = (const float2*)(x   + (size_t)n * CIN * HW + hw);
    float2*       outr = (float2*)      (out + (size_t)n * CIN * HW + hw);

#pragma unroll 2
    for (int o = 0; o < COUT; o++) {
        const uint4* wo = s_w + o * 9;
        int a0 = 0, a1 = 0;
#pragma unroll
        for (int dh = 0; dh < 3; dh++) {
#pragma unroll
            for (int dw = 0; dw < 3; dw++) {
                uint4 wv = wo[dh * 3 + dw];
                uint4 v0 = nb[dh * 4 + dw];
                uint4 v1 = nb[dh * 4 + dw + 1];
                a0 += __popc(v0.x ^ wv.x) + __popc(v0.y ^ wv.y)
                    + __popc(v0.z ^ wv.z) + __popc(v0.w ^ wv.w);
                a1 += __popc(v1.x ^ wv.x) + __popc(v1.y ^ wv.y)
                    + __popc(v1.z ^ wv.z) + __popc(v1.w ^ wv.w);
            }
        }
        float2 res = xr[(size_t)o * (HW / 2)];
        float  A2  = s_A[o];
        float2 r;
        r.x = fmaf(A2, (float)a0, bc0[o]) + res.x;
        r.y = fmaf(A2, (float)a1, bc1[o]) + res.y;
        outr[(size_t)o * (HW / 2)] = r;
    }
}

// ---------------------------------------------------------------------------
extern "C" void kernel_launch(void* const* d_in, const int* in_sizes, int n_in,
                              void* d_out, int out_size) {
    const float* x       = (const float*)d_in[0];
    const float* weight  = (const float*)d_in[1];
    const float* gamma   = (const float*)d_in[2];
    const float* beta    = (const float*)d_in[3];
    const float* bn_mean = (const float*)d_in[4];
    const float* bn_var  = (const float*)d_in[5];
    float* out = (float*)d_out;

    (void)in_sizes; (void)n_in; (void)out_size;

    // fused zero+pack: 215296 padded cells
    pack_x_kernel<<<842, 256>>>(x);
    prep_w_kernel<<<COUT, 128>>>(weight, gamma, beta, bn_mean, bn_var);
    // 100352 pixel pairs -> 784 blocks * 128
    conv_kernel<<<784, 128>>>(x, out);
}

// round 7
// speedup vs baseline: 1.1682x; 1.1682x over previous
#include <cuda_runtime.h>
#include <cstdint>

#define N_IMG 64
#define CIN   128
#define COUT  128
#define HH    56
#define WW    56
#define HW    (HH*WW)      /* 3136 */
#define HP    58
#define WP    58
#define PHW   (HP*WP)      /* 3364 */

// Padded packed sign bits of activation: [n][hp][wp] -> uint4 (128 channels, bit=1 means +1)
__device__ uint4 g_px[N_IMG * PHW];          // 3.44 MB
// Packed sign bits of weights: [o][tap] -> uint4
__device__ uint4 g_pw[COUT * 9];
// Per-channel factor: -2 * scale_o * bn_inv
__device__ float g_A[COUT];
// Border-type-folded bias (includes +1152*A term): [type 0..8][o]
__device__ float g_Bc[9 * COUT];

// ---------------------------------------------------------------------------
// Kernel 1: fused zero+pack over the padded array. One thread per padded cell.
// ---------------------------------------------------------------------------
__global__ void pack_x_kernel(const float* __restrict__ x) {
    int i = blockIdx.x * 256 + threadIdx.x;          // 0 .. 215295
    if (i >= N_IMG * PHW) return;
    int n  = i / PHW;
    int c  = i - n * PHW;
    int hp = c / WP, wp = c - hp * WP;
    if (hp == 0 || hp == HP - 1 || wp == 0 || wp == WP - 1) {
        g_px[i] = make_uint4(0u, 0u, 0u, 0u);
        return;
    }
    int hw = (hp - 1) * WW + (wp - 1);
    const float* xp = x + (size_t)n * CIN * HW + hw;

    uint32_t w0 = 0u, w1 = 0u, w2 = 0u, w3 = 0u;
#pragma unroll 8
    for (int cc = 0; cc < 32; cc++) {
        w0 |= ((__float_as_uint(xp[(size_t)(cc      ) * HW]) >> 31) ^ 1u) << cc;
        w1 |= ((__float_as_uint(xp[(size_t)(cc + 32 ) * HW]) >> 31) ^ 1u) << cc;
        w2 |= ((__float_as_uint(xp[(size_t)(cc + 64 ) * HW]) >> 31) ^ 1u) << cc;
        w3 |= ((__float_as_uint(xp[(size_t)(cc + 96 ) * HW]) >> 31) ^ 1u) << cc;
    }
    g_px[i] = make_uint4(w0, w1, w2, w3);
}

// ---------------------------------------------------------------------------
// Kernel 2: weight prep. One block (128 threads) per output channel.
// ---------------------------------------------------------------------------
__global__ void prep_w_kernel(const float* __restrict__ wgt,
                              const float* __restrict__ gamma,
                              const float* __restrict__ beta,
                              const float* __restrict__ bn_mean,
                              const float* __restrict__ bn_var) {
    int o   = blockIdx.x;
    int tid = threadIdx.x;                      // 128 threads
    __shared__ float s_red[128];
    __shared__ int   s_wpop[9];
    __shared__ float sA, sBb;

    const float* wo = wgt + (size_t)o * CIN * 9;

    float s = 0.f;
#pragma unroll
    for (int t = 0; t < 9; t++) s += fabsf(wo[tid * 9 + t]);
    s_red[tid] = s;
    __syncthreads();
    for (int k = 64; k > 0; k >>= 1) {
        if (tid < k) s_red[tid] += s_red[tid + k];
        __syncthreads();
    }

    if (tid < 9) {
        int t = tid;
        uint32_t wd[4] = {0u, 0u, 0u, 0u};
        for (int c = 0; c < CIN; c++) {
            uint32_t b = ((__float_as_uint(wo[(size_t)c * 9 + t]) >> 31) ^ 1u) & 1u;
            wd[c >> 5] |= b << (c & 31);
        }
        g_pw[o * 9 + t] = make_uint4(wd[0], wd[1], wd[2], wd[3]);
        s_wpop[t] = __popc(wd[0]) + __popc(wd[1]) + __popc(wd[2]) + __popc(wd[3]);
    }
    if (tid == 0) {
        float scale = s_red[0] * (1.0f / 1152.0f);
        float inv   = gamma[o] * rsqrtf(bn_var[o] + 1e-5f);
        sA  = scale * inv;
        sBb = beta[o] - bn_mean[o] * inv;
        g_A[o] = -2.0f * sA;                 // folded: r = A*(1152-2acc)+B = (-2A)*acc + (B+1152A)
    }
    __syncthreads();

    if (tid < 9) {
        int type = tid;
        int rt = type / 3, ct = type - rt * 3;
        int corr = 0;
#pragma unroll
        for (int t = 0; t < 9; t++) {
            int dh = t / 3, dw = t - dh * 3;
            bool inval = (rt == 0 && dh == 0) || (rt == 2 && dh == 2) ||
                         (ct == 0 && dw == 0) || (ct == 2 && dw == 2);
            if (inval) corr += 128 - 2 * s_wpop[t];
        }
        g_Bc[type * COUT + o] = sBb - sA * (float)corr + 1152.0f * sA;
    }
}

// ---------------------------------------------------------------------------
// Kernel 3: XNOR-popcount conv + BN + residual.
// Block (128,2): tid.x = pixel within block, tid.y = output-channel half.
// Each thread: one pixel, 64 output channels. More warps -> better latency
// hiding; nb[9] stays in registers; weight LDS is warp-uniform broadcast.
// ---------------------------------------------------------------------------
__global__ __launch_bounds__(256) void conv_kernel(const float* __restrict__ x,
                                                   float* __restrict__ out) {
    __shared__ uint4 s_w[COUT * 9];      // 18 KB
    __shared__ float s_A[COUT];
    __shared__ float s_Bc[9 * COUT];     // 4.5 KB

    int tid = threadIdx.y * 128 + threadIdx.x;
    for (int i = tid; i < COUT * 9; i += 256) s_w[i] = g_pw[i];
    for (int i = tid; i < COUT;     i += 256) s_A[i] = g_A[i];
    for (int i = tid; i < 9 * COUT; i += 256) s_Bc[i] = g_Bc[i];
    __syncthreads();

    int p = blockIdx.x * 128 + threadIdx.x;  // 0 .. 200703 (grid exact: 1568*128)
    int n  = p / HW;
    int hw = p - n * HW;
    int h = hw / WW, w = hw - (hw / WW) * WW;

    // 3x3 neighborhood of packed activations (zero-padded)
    const uint4* pxn = g_px + n * PHW + h * WP + w;
    uint4 nb[9];
#pragma unroll
    for (int dh = 0; dh < 3; dh++)
#pragma unroll
        for (int dw = 0; dw < 3; dw++)
            nb[dh * 3 + dw] = pxn[dh * WP + dw];

    int rt = (h == 0) ? 0 : ((h == HH - 1) ? 2 : 1);
    int ct = (w == 0) ? 0 : ((w == WW - 1) ? 2 : 1);
    const float* bc = s_Bc + (rt * 3 + ct) * COUT;

    int o0 = threadIdx.y * (COUT / 2);       // 0 or 64
    const float* xr   = x   + (size_t)n * CIN * HW + (size_t)o0 * HW + hw;
    float*       outr = out + (size_t)n * CIN * HW + (size_t)o0 * HW + hw;

#pragma unroll 4
    for (int oo = 0; oo < COUT / 2; oo++) {
        int o = o0 + oo;
        const uint4* wo = s_w + o * 9;
        int acc = 0;
#pragma unroll
        for (int t = 0; t < 9; t++) {
            uint4 wv = wo[t];
            uint4 av = nb[t];
            acc += __popc(av.x ^ wv.x) + __popc(av.y ^ wv.y)
                 + __popc(av.z ^ wv.z) + __popc(av.w ^ wv.w);
        }
        float r = fmaf(s_A[o], (float)acc, bc[o]) + xr[(size_t)oo * HW];
        outr[(size_t)oo * HW] = r;
    }
}

// ---------------------------------------------------------------------------
extern "C" void kernel_launch(void* const* d_in, const int* in_sizes, int n_in,
                              void* d_out, int out_size) {
    const float* x       = (const float*)d_in[0];
    const float* weight  = (const float*)d_in[1];
    const float* gamma   = (const float*)d_in[2];
    const float* beta    = (const float*)d_in[3];
    const float* bn_mean = (const float*)d_in[4];
    const float* bn_var  = (const float*)d_in[5];
    float* out = (float*)d_out;

    (void)in_sizes; (void)n_in; (void)out_size;

    // fused zero+pack: 215296 padded cells
    pack_x_kernel<<<842, 256>>>(x);
    prep_w_kernel<<<COUT, 128>>>(weight, gamma, beta, bn_mean, bn_var);
    // 200704 pixels, 128 pixels per block, o-split in 2 halves
    dim3 blk(128, 2);
    conv_kernel<<<1568, blk>>>(x, out);
}